// round 8
// baseline (speedup 1.0000x reference)
#include <cuda_runtime.h>
#include <cuda_bf16.h>
#include <cstdint>

// CenterLoss: mean_b clip(||x_b - centers[labels[b]]||^2, 1e-12, 1e12)
// x: [B, D] f32, labels: [B] i32, centers: [C, D] f32 -> scalar f32.
// Concurrency-optimized: 1 sample/warp (8192 warps), all 8 float4 loads
// batched per lane, 256-thread blocks capped at 48 regs for 40 warps/SM,
// fused deterministic last-block reduction.

#define CLAMP_MIN 1e-12f
#define CLAMP_MAX 1e12f

#define WPB        8                     // warps per block
#define BLOCK_THR  (WPB * 32)            // 256
#define MAX_BLOCKS 16384

__device__ float        g_partials[MAX_BLOCKS];
__device__ unsigned int g_done_count = 0;

__global__ __launch_bounds__(BLOCK_THR, 5)   // <=48 regs -> 5 blocks/SM -> 62% occ
void center_loss_kernel(const float* __restrict__ x,
                        const int* __restrict__ labels,
                        const float* __restrict__ centers,
                        float* __restrict__ out,
                        int B, int D, int C, float inv_B)
{
    const int lane = threadIdx.x & 31;
    const int warp = threadIdx.x >> 5;
    const int b    = blockIdx.x * WPB + warp;    // one sample per warp

    float dist = 0.0f;
    if (b < B) {
        // x loads are label-independent: issue them first.
        const float4* __restrict__ xr = (const float4*)(x + (size_t)b * D);
        float4 x0 = __ldg(&xr[lane +  0]);
        float4 x1 = __ldg(&xr[lane + 32]);
        float4 x2 = __ldg(&xr[lane + 64]);
        float4 x3 = __ldg(&xr[lane + 96]);

        // Warp-uniform broadcast load of the label (overlaps with x loads).
        int lbl = __ldg(labels + b);
        lbl = min(max(lbl, 0), C - 1);

        const float4* __restrict__ cr = (const float4*)(centers + (size_t)lbl * D);
        float4 c0 = __ldg(&cr[lane +  0]);
        float4 c1 = __ldg(&cr[lane + 32]);
        float4 c2 = __ldg(&cr[lane + 64]);
        float4 c3 = __ldg(&cr[lane + 96]);

        float a0 = 0.f, a1 = 0.f, a2 = 0.f, a3 = 0.f;
        float t;
        t = x0.x - c0.x; a0 = fmaf(t, t, a0);
        t = x0.y - c0.y; a1 = fmaf(t, t, a1);
        t = x0.z - c0.z; a2 = fmaf(t, t, a2);
        t = x0.w - c0.w; a3 = fmaf(t, t, a3);
        t = x1.x - c1.x; a0 = fmaf(t, t, a0);
        t = x1.y - c1.y; a1 = fmaf(t, t, a1);
        t = x1.z - c1.z; a2 = fmaf(t, t, a2);
        t = x1.w - c1.w; a3 = fmaf(t, t, a3);
        t = x2.x - c2.x; a0 = fmaf(t, t, a0);
        t = x2.y - c2.y; a1 = fmaf(t, t, a1);
        t = x2.z - c2.z; a2 = fmaf(t, t, a2);
        t = x2.w - c2.w; a3 = fmaf(t, t, a3);
        t = x3.x - c3.x; a0 = fmaf(t, t, a0);
        t = x3.y - c3.y; a1 = fmaf(t, t, a1);
        t = x3.z - c3.z; a2 = fmaf(t, t, a2);
        t = x3.w - c3.w; a3 = fmaf(t, t, a3);

        dist = (a0 + a1) + (a2 + a3);
    }

    // Warp reduce.
    #pragma unroll
    for (int off = 16; off > 0; off >>= 1)
        dist += __shfl_xor_sync(0xFFFFFFFFu, dist, off);

    __shared__ float s_warp[WPB];
    if (lane == 0) {
        float d = fminf(fmaxf(dist, CLAMP_MIN), CLAMP_MAX);  // per-sample clip
        if (b >= B) d = 0.0f;
        s_warp[warp] = d;
    }
    __syncthreads();

    __shared__ bool s_is_last;
    if (threadIdx.x == 0) {
        float v = 0.0f;
        #pragma unroll
        for (int w = 0; w < WPB; w++) v += s_warp[w];
        g_partials[blockIdx.x] = v;
        __threadfence();
        unsigned int prev = atomicAdd(&g_done_count, 1u);
        s_is_last = (prev == gridDim.x - 1);
    }
    __syncthreads();

    // Deterministic fixed-order final reduction by the last block to finish.
    if (s_is_last) {
        const int tid = threadIdx.x;
        const int nblocks = gridDim.x;

        float v = 0.0f;
        for (int i = tid; i < nblocks; i += BLOCK_THR)
            v += g_partials[i];

        #pragma unroll
        for (int off = 16; off > 0; off >>= 1)
            v += __shfl_xor_sync(0xFFFFFFFFu, v, off);

        __shared__ float s_fin[WPB];
        if (lane == 0) s_fin[warp] = v;
        __syncthreads();

        if (tid == 0) {
            float w = 0.0f;
            #pragma unroll
            for (int i = 0; i < WPB; i++) w += s_fin[i];
            out[0] = w * inv_B;
            g_done_count = 0;   // reset for next graph replay
        }
    }
}

extern "C" void kernel_launch(void* const* d_in, const int* in_sizes, int n_in,
                              void* d_out, int out_size)
{
    const float* x       = (const float*)d_in[0];
    const int*   labels  = (const int*)d_in[1];
    const float* centers = (const float*)d_in[2];
    float*       out     = (float*)d_out;

    const int B = in_sizes[1];                 // 8192
    const int D = in_sizes[0] / B;             // 512
    const int C = in_sizes[2] / D;             // 10000

    int nblocks = (B + WPB - 1) / WPB;         // 1024
    if (nblocks > MAX_BLOCKS) nblocks = MAX_BLOCKS;

    center_loss_kernel<<<nblocks, BLOCK_THR>>>(
        x, labels, centers, out, B, D, C, 1.0f / (float)B);
}

// round 9
// speedup vs baseline: 1.1384x; 1.1384x over previous
#include <cuda_runtime.h>
#include <cuda_bf16.h>
#include <cstdint>

// CenterLoss: mean_b clip(||x_b - centers[labels[b]]||^2, 1e-12, 1e12)
// x: [B, D] f32, labels: [B] i32, centers: [C, D] f32 -> scalar f32.
// Software-pipelined: each warp owns 4 consecutive samples; labels hoisted
// (one int4 per warp), x/center rows double-buffered in registers so sample
// k+1's loads fly while sample k computes. One wave: 128 blocks x 512 thr.

#define CLAMP_MIN 1e-12f
#define CLAMP_MAX 1e12f

#define WPB        16                    // warps per block
#define BLOCK_THR  (WPB * 32)            // 512
#define SPW        4                     // consecutive samples per warp
#define MAX_BLOCKS 16384

__device__ float        g_partials[MAX_BLOCKS];
__device__ unsigned int g_done_count = 0;

__global__ __launch_bounds__(BLOCK_THR)
void center_loss_kernel(const float* __restrict__ x,
                        const int* __restrict__ labels,
                        const float* __restrict__ centers,
                        float* __restrict__ out,
                        int B, int D, int C, float inv_B)
{
    const int lane = threadIdx.x & 31;
    const int warp = threadIdx.x >> 5;
    const int gw   = blockIdx.x * WPB + warp;
    const int s0   = gw * SPW;

    float total = 0.0f;   // lane 0 accumulates clipped per-sample distances

    if (s0 < B) {
        // ── Hoist all labels for this warp: one int4 by lane 0, broadcast ──
        int4 labs = make_int4(0, 0, 0, 0);
        if (lane == 0) {
            if (s0 + SPW <= B) {
                labs = __ldg((const int4*)(labels + s0));
            } else {
                labs.x = __ldg(labels + s0);
                if (s0 + 1 < B) labs.y = __ldg(labels + s0 + 1);
                if (s0 + 2 < B) labs.z = __ldg(labels + s0 + 2);
                if (s0 + 3 < B) labs.w = __ldg(labels + s0 + 3);
            }
        }
        int lbl[SPW];
        lbl[0] = __shfl_sync(0xFFFFFFFFu, labs.x, 0);
        lbl[1] = __shfl_sync(0xFFFFFFFFu, labs.y, 0);
        lbl[2] = __shfl_sync(0xFFFFFFFFu, labs.z, 0);
        lbl[3] = __shfl_sync(0xFFFFFFFFu, labs.w, 0);
        #pragma unroll
        for (int k = 0; k < SPW; k++)
            lbl[k] = min(max(lbl[k], 0), C - 1);

        // ── Double-buffered register tiles: 4 float4 of x + 4 of center ──
        float4 xb[2][4], cb[2][4];

        // Pipeline fill: sample 0
        {
            const float4* __restrict__ xr = (const float4*)(x + (size_t)s0 * D);
            const float4* __restrict__ cr = (const float4*)(centers + (size_t)lbl[0] * D);
            #pragma unroll
            for (int j = 0; j < 4; j++) {
                xb[0][j] = __ldg(&xr[lane + 32 * j]);
                cb[0][j] = __ldg(&cr[lane + 32 * j]);
            }
        }

        #pragma unroll
        for (int k = 0; k < SPW; k++) {
            const int cur = k & 1;
            const int nxt = cur ^ 1;

            // Prefetch sample k+1 while computing sample k.
            if (k + 1 < SPW && s0 + k + 1 < B) {
                const float4* __restrict__ xr =
                    (const float4*)(x + (size_t)(s0 + k + 1) * D);
                const float4* __restrict__ cr =
                    (const float4*)(centers + (size_t)lbl[k + 1] * D);
                #pragma unroll
                for (int j = 0; j < 4; j++) {
                    xb[nxt][j] = __ldg(&xr[lane + 32 * j]);
                    cb[nxt][j] = __ldg(&cr[lane + 32 * j]);
                }
            }

            if (s0 + k < B) {
                float a0 = 0.f, a1 = 0.f, a2 = 0.f, a3 = 0.f;
                #pragma unroll
                for (int j = 0; j < 4; j++) {
                    float t;
                    t = xb[cur][j].x - cb[cur][j].x; a0 = fmaf(t, t, a0);
                    t = xb[cur][j].y - cb[cur][j].y; a1 = fmaf(t, t, a1);
                    t = xb[cur][j].z - cb[cur][j].z; a2 = fmaf(t, t, a2);
                    t = xb[cur][j].w - cb[cur][j].w; a3 = fmaf(t, t, a3);
                }
                float dist = (a0 + a1) + (a2 + a3);
                #pragma unroll
                for (int off = 16; off > 0; off >>= 1)
                    dist += __shfl_xor_sync(0xFFFFFFFFu, dist, off);
                if (lane == 0)
                    total += fminf(fmaxf(dist, CLAMP_MIN), CLAMP_MAX);
            }
        }
    }

    // ── Block reduction of per-warp totals (lane-0 values) ──
    __shared__ float s_warp[WPB];
    if (lane == 0) s_warp[warp] = total;
    __syncthreads();

    __shared__ bool s_is_last;
    if (threadIdx.x == 0) {
        float v = 0.0f;
        #pragma unroll
        for (int w = 0; w < WPB; w++) v += s_warp[w];
        g_partials[blockIdx.x] = v;
        __threadfence();
        unsigned int prev = atomicAdd(&g_done_count, 1u);
        s_is_last = (prev == gridDim.x - 1);
    }
    __syncthreads();

    // Deterministic fixed-order final reduction by the last block to finish.
    if (s_is_last) {
        const int tid = threadIdx.x;
        const int nblocks = gridDim.x;

        float v = 0.0f;
        for (int i = tid; i < nblocks; i += BLOCK_THR)
            v += g_partials[i];

        #pragma unroll
        for (int off = 16; off > 0; off >>= 1)
            v += __shfl_xor_sync(0xFFFFFFFFu, v, off);

        __shared__ float s_fin[WPB];
        if (lane == 0) s_fin[warp] = v;
        __syncthreads();

        if (tid == 0) {
            float w = 0.0f;
            #pragma unroll
            for (int i = 0; i < WPB; i++) w += s_fin[i];
            out[0] = w * inv_B;
            g_done_count = 0;   // reset for next graph replay
        }
    }
}

extern "C" void kernel_launch(void* const* d_in, const int* in_sizes, int n_in,
                              void* d_out, int out_size)
{
    const float* x       = (const float*)d_in[0];
    const int*   labels  = (const int*)d_in[1];
    const float* centers = (const float*)d_in[2];
    float*       out     = (float*)d_out;

    const int B = in_sizes[1];                 // 8192
    const int D = in_sizes[0] / B;             // 512
    const int C = in_sizes[2] / D;             // 10000

    const int samples_per_block = WPB * SPW;   // 64
    int nblocks = (B + samples_per_block - 1) / samples_per_block;   // 128
    if (nblocks > MAX_BLOCKS) nblocks = MAX_BLOCKS;

    center_loss_kernel<<<nblocks, BLOCK_THR>>>(
        x, labels, centers, out, B, D, C, 1.0f / (float)B);
}